// round 3
// baseline (speedup 1.0000x reference)
#include <cuda_runtime.h>
#include <math.h>

// Shapes (fixed by the problem)
#define Bc 2
#define Tc 2048
#define Sc 2048
#define Cc 1024
#define Hc 16
#define HDc 64
#define BHc (Bc*Hc)          // 32
#define NSPLIT 16            // split-K over S for M / Ksum partials (deterministic)

// ---------------- scratch (device globals; no allocation allowed) ----------------
__device__ float g_Q [Bc*Tc*Cc];            // raw Q projection        (16 MB)
__device__ float g_KV[Bc*Sc*2*Cc];          // raw KV; K half -> K_rot (32 MB)
__device__ float g_Y [Bc*Tc*Cc];            // per-head outputs, [B,T,C] layout (16 MB)
__device__ float g_cos[Sc*32];
__device__ float g_sin[Sc*32];
__device__ float g_Kpart[NSPLIT][BHc*HDc];  // partial sums of elu(K)+1 over s
__device__ float g_Ksum [BHc*HDc];
__device__ float g_Mpart[NSPLIT][BHc*HDc*HDc]; // partial K_rot^T V   (8 MB)
__device__ float g_M    [BHc*HDc*HDc];

__device__ __forceinline__ float eluplus(float x) {
    return x > 0.0f ? x + 1.0f : expf(x);
}

// ---------------- rope cos/sin table (mimic jax fp32 computation) ----------------
__global__ void rope_table_kernel() {
    int idx = blockIdx.x * blockDim.x + threadIdx.x;
    if (idx >= Sc * 32) return;
    int t = idx >> 5, j = idx & 31;
    float ex   = (float)(2 * j) / 64.0f;           // arange(0,dim,2)/dim
    float invf = 1.0f / powf(10000.0f, ex);
    float ang  = (float)t * invf;                  // fp32 product, like jnp.outer
    float s, c;
    sincosf(ang, &s, &c);
    g_cos[idx] = c;
    g_sin[idx] = s;
}

// ---------------- fp32 SGEMM: C = A[MxK] @ W[KxN] + bias ----------------
// 128x128 block tile, BK=8, 8x8 per thread, 256 threads.
__global__ __launch_bounds__(256, 2)
void sgemm_bias_kernel(const float* __restrict__ A, const float* __restrict__ W,
                       const float* __restrict__ bias, float* __restrict__ C,
                       int M, int N, int K) {
    __shared__ float As[8][132];   // transposed A tile, padded (132*4B = 33*16B)
    __shared__ float Bs[8][128];

    const int tid = threadIdx.x;
    const int n0  = blockIdx.x * 128;
    const int m0  = blockIdx.y * 128;
    const int tm  = tid >> 4;      // 0..15
    const int tn  = tid & 15;      // 0..15

    float acc[8][8];
#pragma unroll
    for (int i = 0; i < 8; i++)
#pragma unroll
        for (int j = 0; j < 8; j++) acc[i][j] = 0.0f;

    const int arow = tid >> 1;         // 0..127
    const int acol = (tid & 1) * 4;    // 0 or 4
    const int brow = tid >> 5;         // 0..7
    const int bcol = (tid & 31) * 4;   // 0..124

    const float* Aptr = A + (size_t)(m0 + arow) * K + acol;
    const float* Wptr = W + (size_t)brow * N + n0 + bcol;

    for (int k0 = 0; k0 < K; k0 += 8) {
        float4 av = *(const float4*)(Aptr + k0);
        As[acol + 0][arow] = av.x;
        As[acol + 1][arow] = av.y;
        As[acol + 2][arow] = av.z;
        As[acol + 3][arow] = av.w;
        float4 bv = *(const float4*)(Wptr + (size_t)k0 * N);
        *(float4*)&Bs[brow][bcol] = bv;
        __syncthreads();

#pragma unroll
        for (int k = 0; k < 8; k++) {
            float4 a0 = *(const float4*)&As[k][tm * 8];
            float4 a1 = *(const float4*)&As[k][tm * 8 + 4];
            float4 b0 = *(const float4*)&Bs[k][tn * 8];
            float4 b1 = *(const float4*)&Bs[k][tn * 8 + 4];
            float a[8] = {a0.x, a0.y, a0.z, a0.w, a1.x, a1.y, a1.z, a1.w};
            float bb[8] = {b0.x, b0.y, b0.z, b0.w, b1.x, b1.y, b1.z, b1.w};
#pragma unroll
            for (int i = 0; i < 8; i++)
#pragma unroll
                for (int j = 0; j < 8; j++) acc[i][j] += a[i] * bb[j];
        }
        __syncthreads();
    }

    float4 bi0 = *(const float4*)&bias[n0 + tn * 8];
    float4 bi1 = *(const float4*)&bias[n0 + tn * 8 + 4];
#pragma unroll
    for (int i = 0; i < 8; i++) {
        int row = m0 + tm * 8 + i;
        float* cp = C + (size_t)row * N + n0 + tn * 8;
        float4 o0 = make_float4(acc[i][0] + bi0.x, acc[i][1] + bi0.y,
                                acc[i][2] + bi0.z, acc[i][3] + bi0.w);
        float4 o1 = make_float4(acc[i][4] + bi1.x, acc[i][5] + bi1.y,
                                acc[i][6] + bi1.z, acc[i][7] + bi1.w);
        *(float4*)cp       = o0;
        *(float4*)(cp + 4) = o1;
    }
}

// ---------------- K: elu+1, rope in-place, partial column sums ----------------
// grid (BH, NSPLIT), 256 threads; tid%32 = pair index j, tid/32 = s subgroup
__global__ __launch_bounds__(256)
void prep_k_kernel() {
    const int bh = blockIdx.x, split = blockIdx.y;
    const int b = bh >> 4, h = bh & 15;
    const int tid = threadIdx.x;
    const int j = tid & 31, sg = tid >> 5;   // j: 0..31, sg: 0..7
    float acc1 = 0.0f, acc2 = 0.0f;
#pragma unroll 4
    for (int it = 0; it < 16; it++) {
        int s = split * 128 + sg + it * 8;
        int addr = (b * Sc + s) * 2048 + h * 64 + j;
        float k1 = g_KV[addr], k2 = g_KV[addr + 32];
        float e1 = eluplus(k1), e2 = eluplus(k2);
        float c  = g_cos[s * 32 + j], si = g_sin[s * 32 + j];
        g_KV[addr]      = e1 * c - e2 * si;
        g_KV[addr + 32] = e2 * c + e1 * si;
        acc1 += e1;
        acc2 += e2;
    }
    __shared__ float r1[256], r2[256];
    r1[tid] = acc1;
    r2[tid] = acc2;
    __syncthreads();
    if (tid < 32) {
        float s1 = 0.0f, s2 = 0.0f;
#pragma unroll
        for (int g = 0; g < 8; g++) { s1 += r1[tid + 32 * g]; s2 += r2[tid + 32 * g]; }
        g_Kpart[split][bh * 64 + tid]      = s1;
        g_Kpart[split][bh * 64 + tid + 32] = s2;
    }
}

// ---------------- Mpart[split][bh] = K_rot[slice]^T @ V[slice]  (64x64) ----------------
// grid (BH, NSPLIT), 256 threads: 16x16 thread grid, 4x4 per thread, k-tile 16
__global__ __launch_bounds__(256)
void compute_mpart_kernel() {
    const int bh = blockIdx.x, split = blockIdx.y;
    const int b = bh >> 4, h = bh & 15;
    __shared__ float Ksm[16][64];
    __shared__ float Vsm[16][68];
    const int tid = threadIdx.x;
    const int ti = tid >> 4;          // i group (K_rot dim)
    const int td = tid & 15;          // d group (V dim)
    const int lrow = tid >> 4;        // 0..15 for loads
    const int lc = (tid & 15) * 4;

    float acc[4][4];
#pragma unroll
    for (int i = 0; i < 4; i++)
#pragma unroll
        for (int j = 0; j < 4; j++) acc[i][j] = 0.0f;

    for (int kt = 0; kt < 8; kt++) {
        int s = split * 128 + kt * 16 + lrow;
        const float* kp = &g_KV[(b * Sc + s) * 2048 + h * 64 + lc];
        float4 kv = *(const float4*)kp;
        float4 vv = *(const float4*)(kp + 1024);
        *(float4*)&Ksm[lrow][lc] = kv;
        *(float4*)&Vsm[lrow][lc] = vv;
        __syncthreads();
#pragma unroll
        for (int k = 0; k < 16; k++) {
            float4 a4 = *(const float4*)&Ksm[k][ti * 4];
            float4 b4 = *(const float4*)&Vsm[k][td * 4];
            float a[4] = {a4.x, a4.y, a4.z, a4.w};
            float bb[4] = {b4.x, b4.y, b4.z, b4.w};
#pragma unroll
            for (int i = 0; i < 4; i++)
#pragma unroll
                for (int j = 0; j < 4; j++) acc[i][j] += a[i] * bb[j];
        }
        __syncthreads();
    }
    float* mp = &g_Mpart[split][bh * 4096];
#pragma unroll
    for (int i = 0; i < 4; i++) {
        float4 o = make_float4(acc[i][0], acc[i][1], acc[i][2], acc[i][3]);
        *(float4*)&mp[(ti * 4 + i) * 64 + td * 4] = o;
    }
}

// ---------------- reduce split-K partials (deterministic) ----------------
__global__ void reduce_parts_kernel() {
    int idx = blockIdx.x * 256 + threadIdx.x;
    if (idx < BHc * 4096) {
        float s = 0.0f;
#pragma unroll
        for (int sp = 0; sp < NSPLIT; sp++) s += g_Mpart[sp][idx];
        g_M[idx] = s;
    } else if (idx < BHc * 4096 + BHc * 64) {
        int i2 = idx - BHc * 4096;
        float s = 0.0f;
#pragma unroll
        for (int sp = 0; sp < NSPLIT; sp++) s += g_Kpart[sp][i2];
        g_Ksum[i2] = s;
    }
}

// ---------------- y = (rope(elu(Q)+1) @ M) / (elu(Q)+1 . Ksum) ----------------
// grid (BH, T/64), 256 threads. Processes 64 query rows of one head.
__global__ __launch_bounds__(256)
void compute_y_kernel() {
    const int bh = blockIdx.x, tchunk = blockIdx.y;
    const int b = bh >> 4, h = bh & 15;
    const int t0 = tchunk * 64;
    __shared__ float smA[64 * 65];   // phase 1: qelu (stride 65); phase 2: M (4096, stride 64)
    __shared__ float qrot[64 * 65];
    __shared__ float ks[64];
    __shared__ float den[64];
    const int tid = threadIdx.x;

    if (tid < 64) ks[tid] = g_Ksum[bh * 64 + tid];

    // load Q tile, apply elu+1
#pragma unroll
    for (int it = 0; it < 4; it++) {
        int idx = tid + it * 256;                 // 0..1023
        int r = idx >> 4, c4 = (idx & 15) * 4;
        float4 qv = *(const float4*)&g_Q[(b * Tc + t0 + r) * 1024 + h * 64 + c4];
        smA[r * 65 + c4 + 0] = eluplus(qv.x);
        smA[r * 65 + c4 + 1] = eluplus(qv.y);
        smA[r * 65 + c4 + 2] = eluplus(qv.z);
        smA[r * 65 + c4 + 3] = eluplus(qv.w);
    }
    __syncthreads();

    // rope into qrot
#pragma unroll
    for (int it = 0; it < 8; it++) {
        int idx = tid + it * 256;                 // 0..2047
        int r = idx >> 5, j = idx & 31;
        float e1 = smA[r * 65 + j], e2 = smA[r * 65 + j + 32];
        int t = t0 + r;
        float c = g_cos[t * 32 + j], si = g_sin[t * 32 + j];
        qrot[r * 65 + j]      = e1 * c - e2 * si;
        qrot[r * 65 + j + 32] = e2 * c + e1 * si;
    }
    // denom per row (tid<64), deterministic serial dot
    if (tid < 64) {
        float s = 0.0f;
#pragma unroll
        for (int d = 0; d < 64; d++) s += smA[tid * 65 + d] * ks[d];
        den[tid] = s;
    }
    __syncthreads();

    // load M over qelu (no longer needed)
#pragma unroll
    for (int it = 0; it < 16; it++) {
        int idx = tid + it * 256;
        smA[idx] = g_M[bh * 4096 + idx];
    }
    __syncthreads();

    // matvec: row = tid/4, 16 output dims per thread
    const int row = tid >> 2;
    const int dg = (tid & 3) * 16;
    float acc[16];
#pragma unroll
    for (int i = 0; i < 16; i++) acc[i] = 0.0f;
#pragma unroll
    for (int k = 0; k < 64; k++) {
        float qv = qrot[row * 65 + k];
#pragma unroll
        for (int q = 0; q < 4; q++) {
            float4 mv = *(const float4*)&smA[k * 64 + dg + q * 4];
            acc[q * 4 + 0] += qv * mv.x;
            acc[q * 4 + 1] += qv * mv.y;
            acc[q * 4 + 2] += qv * mv.z;
            acc[q * 4 + 3] += qv * mv.w;
        }
    }
    float inv = 1.0f / den[row];
    float* yp = &g_Y[(b * Tc + t0 + row) * 1024 + h * 64 + dg];
#pragma unroll
    for (int q = 0; q < 4; q++) {
        float4 o = make_float4(acc[q * 4 + 0] * inv, acc[q * 4 + 1] * inv,
                               acc[q * 4 + 2] * inv, acc[q * 4 + 3] * inv);
        *(float4*)(yp + q * 4) = o;
    }
}

// ---------------- launch ----------------
extern "C" void kernel_launch(void* const* d_in, const int* in_sizes, int n_in,
                              void* d_out, int out_size) {
    const float* x      = (const float*)d_in[0];
    const float* memory = (const float*)d_in[1];
    const float* q_w    = (const float*)d_in[2];
    const float* q_b    = (const float*)d_in[3];
    const float* kv_w   = (const float*)d_in[4];
    const float* kv_b   = (const float*)d_in[5];
    const float* proj_w = (const float*)d_in[6];
    const float* proj_b = (const float*)d_in[7];
    float* out = (float*)d_out;

    float *pQ, *pKV, *pY;
    cudaGetSymbolAddress((void**)&pQ,  g_Q);
    cudaGetSymbolAddress((void**)&pKV, g_KV);
    cudaGetSymbolAddress((void**)&pY,  g_Y);

    // rope tables (independent)
    rope_table_kernel<<<(Sc * 32 + 255) / 256, 256>>>();

    // KV = memory @ kv_w + kv_b   [4096, 2048]
    sgemm_bias_kernel<<<dim3(2048 / 128, 4096 / 128), 256>>>(memory, kv_w, kv_b, pKV,
                                                             Bc * Sc, 2 * Cc, Cc);
    // Q = x @ q_w + q_b           [4096, 1024]
    sgemm_bias_kernel<<<dim3(1024 / 128, 4096 / 128), 256>>>(x, q_w, q_b, pQ,
                                                             Bc * Tc, Cc, Cc);
    // K -> elu+1 -> rope (in place), partial Ksum
    prep_k_kernel<<<dim3(BHc, NSPLIT), 256>>>();
    // M partials = K_rot^T V
    compute_mpart_kernel<<<dim3(BHc, NSPLIT), 256>>>();
    // reduce partials
    reduce_parts_kernel<<<(BHc * 4096 + BHc * 64 + 255) / 256, 256>>>();
    // per-head linear attention
    compute_y_kernel<<<dim3(BHc, Tc / 64), 256>>>();
    // out = Y @ proj_w + proj_b   [4096, 1024]
    sgemm_bias_kernel<<<dim3(1024 / 128, 4096 / 128), 256>>>(pY, proj_w, proj_b, out,
                                                             Bc * Tc, Cc, Cc);
}

// round 4
// speedup vs baseline: 1.2790x; 1.2790x over previous
#include <cuda_runtime.h>
#include <cuda_bf16.h>
#include <mma.h>
#include <math.h>

using namespace nvcuda;

// Shapes (fixed by the problem)
#define Bc 2
#define Tc 2048
#define Sc 2048
#define Cc 1024
#define Hc 16
#define HDc 64
#define BHc (Bc*Hc)          // 32
#define NSPLIT 16            // split-K over S for M / Ksum partials (deterministic)

// ---------------- scratch (device globals; no allocation allowed) ----------------
__device__ float g_Q [Bc*Tc*Cc];            // raw Q projection        (16 MB)
__device__ float g_KV[Bc*Sc*2*Cc];          // raw KV; K half -> K_rot (32 MB)
__device__ float g_Y [Bc*Tc*Cc];            // per-head outputs, [B,T,C] layout (16 MB)
__device__ float g_cos[Sc*32];
__device__ float g_sin[Sc*32];
__device__ float g_Kpart[NSPLIT][BHc*HDc];  // partial sums of elu(K)+1 over s
__device__ float g_Ksum [BHc*HDc];
__device__ float g_Mpart[NSPLIT][BHc*HDc*HDc]; // partial K_rot^T V   (8 MB)
__device__ float g_M    [BHc*HDc*HDc];

__device__ __forceinline__ float eluplus(float x) {
    return x > 0.0f ? x + 1.0f : expf(x);
}

// ---------------- rope cos/sin table (mimic jax fp32 computation) ----------------
__global__ void rope_table_kernel() {
    int idx = blockIdx.x * blockDim.x + threadIdx.x;
    if (idx >= Sc * 32) return;
    int t = idx >> 5, j = idx & 31;
    float ex   = (float)(2 * j) / 64.0f;           // arange(0,dim,2)/dim
    float invf = 1.0f / powf(10000.0f, ex);
    float ang  = (float)t * invf;                  // fp32 product, like jnp.outer
    float s, c;
    sincosf(ang, &s, &c);
    g_cos[idx] = c;
    g_sin[idx] = s;
}

// ================= bf16x3 tensor-core GEMM: C = A[MxK] @ W[KxN] + bias =================
// Block tile 128x128, BK=32. 256 threads = 8 warps in 2(m) x 4(n); each warp 64x32.
// fp32 operands split into bf16 hi/lo on the fly; 3 MMA terms: hi*hi + hi*lo + lo*hi.
#define BM 128
#define BN 128
#define BK 32
#define LDA 40    // padded ldm for A tiles (multiple of 8)
#define LDB 136   // padded ldm for B tiles (multiple of 8)

__global__ __launch_bounds__(256, 1)
void gemm_bf16x3_kernel(const float* __restrict__ A, const float* __restrict__ W,
                        const float* __restrict__ bias, float* __restrict__ C,
                        int M, int N, int K) {
    __shared__ __nv_bfloat16 As_hi[BM * LDA];
    __shared__ __nv_bfloat16 As_lo[BM * LDA];
    __shared__ __nv_bfloat16 Bs_hi[BK * LDB];
    __shared__ __nv_bfloat16 Bs_lo[BK * LDB];
    __shared__ float Csm[8][16 * 16];

    const int tid  = threadIdx.x;
    const int lane = tid & 31;
    const int wid  = tid >> 5;
    const int wm   = wid >> 2;        // 0..1
    const int wn   = wid & 3;         // 0..3
    const int m0   = blockIdx.y * BM;
    const int n0   = blockIdx.x * BN;

    wmma::fragment<wmma::accumulator, 16, 16, 16, float> cf[4][2];
#pragma unroll
    for (int i = 0; i < 4; i++)
#pragma unroll
        for (int j = 0; j < 2; j++) wmma::fill_fragment(cf[i][j], 0.0f);

    // A loader: 128 rows x 32 cols, float4 per thread, 4 passes
    const int arow = tid >> 3;            // 0..31 (+32*p)
    const int acol = (tid & 7) * 4;       // 0..28
    // B loader: 32 rows x 128 cols, float4 per thread, 4 passes
    const int brow = tid >> 5;            // 0..7 (+8*p)
    const int bcol = (tid & 31) * 4;      // 0..124

    for (int k0 = 0; k0 < K; k0 += BK) {
#pragma unroll
        for (int p = 0; p < 4; p++) {
            int r = arow + 32 * p;
            float4 v = *(const float4*)(A + (size_t)(m0 + r) * K + k0 + acol);
            float f[4] = {v.x, v.y, v.z, v.w};
#pragma unroll
            for (int q = 0; q < 4; q++) {
                __nv_bfloat16 hi = __float2bfloat16(f[q]);
                __nv_bfloat16 lo = __float2bfloat16(f[q] - __bfloat162float(hi));
                As_hi[r * LDA + acol + q] = hi;
                As_lo[r * LDA + acol + q] = lo;
            }
        }
#pragma unroll
        for (int p = 0; p < 4; p++) {
            int r = brow + 8 * p;
            float4 v = *(const float4*)(W + (size_t)(k0 + r) * N + n0 + bcol);
            float f[4] = {v.x, v.y, v.z, v.w};
#pragma unroll
            for (int q = 0; q < 4; q++) {
                __nv_bfloat16 hi = __float2bfloat16(f[q]);
                __nv_bfloat16 lo = __float2bfloat16(f[q] - __bfloat162float(hi));
                Bs_hi[r * LDB + bcol + q] = hi;
                Bs_lo[r * LDB + bcol + q] = lo;
            }
        }
        __syncthreads();

#pragma unroll
        for (int kk = 0; kk < BK; kk += 16) {
            wmma::fragment<wmma::matrix_a, 16, 16, 16, __nv_bfloat16, wmma::row_major> ah[4], al[4];
            wmma::fragment<wmma::matrix_b, 16, 16, 16, __nv_bfloat16, wmma::row_major> bh[2], bl[2];
#pragma unroll
            for (int i = 0; i < 4; i++) {
                const int row = wm * 64 + i * 16;
                wmma::load_matrix_sync(ah[i], &As_hi[row * LDA + kk], LDA);
                wmma::load_matrix_sync(al[i], &As_lo[row * LDA + kk], LDA);
            }
#pragma unroll
            for (int j = 0; j < 2; j++) {
                const int col = wn * 32 + j * 16;
                wmma::load_matrix_sync(bh[j], &Bs_hi[kk * LDB + col], LDB);
                wmma::load_matrix_sync(bl[j], &Bs_lo[kk * LDB + col], LDB);
            }
#pragma unroll
            for (int i = 0; i < 4; i++)
#pragma unroll
                for (int j = 0; j < 2; j++) {
                    wmma::mma_sync(cf[i][j], ah[i], bl[j], cf[i][j]);
                    wmma::mma_sync(cf[i][j], al[i], bh[j], cf[i][j]);
                    wmma::mma_sync(cf[i][j], ah[i], bh[j], cf[i][j]);
                }
        }
        __syncthreads();
    }

    // Epilogue: stage fragments through shared, add bias, vector-store
    const int er = lane >> 1;            // 0..15
    const int ec = (lane & 1) * 8;       // 0 or 8
#pragma unroll
    for (int i = 0; i < 4; i++)
#pragma unroll
        for (int j = 0; j < 2; j++) {
            wmma::store_matrix_sync(&Csm[wid][0], cf[i][j], 16, wmma::mem_row_major);
            __syncwarp();
            int gcol = n0 + wn * 32 + j * 16 + ec;
            int grow = m0 + wm * 64 + i * 16 + er;
            float4 v0 = *(float4*)&Csm[wid][er * 16 + ec];
            float4 v1 = *(float4*)&Csm[wid][er * 16 + ec + 4];
            float4 b0 = *(const float4*)&bias[gcol];
            float4 b1 = *(const float4*)&bias[gcol + 4];
            v0.x += b0.x; v0.y += b0.y; v0.z += b0.z; v0.w += b0.w;
            v1.x += b1.x; v1.y += b1.y; v1.z += b1.z; v1.w += b1.w;
            float* dst = C + (size_t)grow * N + gcol;
            *(float4*)dst = v0;
            *(float4*)(dst + 4) = v1;
            __syncwarp();
        }
}

// ---------------- K: elu+1, rope in-place, partial column sums ----------------
__global__ __launch_bounds__(256)
void prep_k_kernel() {
    const int bh = blockIdx.x, split = blockIdx.y;
    const int b = bh >> 4, h = bh & 15;
    const int tid = threadIdx.x;
    const int j = tid & 31, sg = tid >> 5;   // j: 0..31, sg: 0..7
    float acc1 = 0.0f, acc2 = 0.0f;
#pragma unroll 4
    for (int it = 0; it < 16; it++) {
        int s = split * 128 + sg + it * 8;
        int addr = (b * Sc + s) * 2048 + h * 64 + j;
        float k1 = g_KV[addr], k2 = g_KV[addr + 32];
        float e1 = eluplus(k1), e2 = eluplus(k2);
        float c  = g_cos[s * 32 + j], si = g_sin[s * 32 + j];
        g_KV[addr]      = e1 * c - e2 * si;
        g_KV[addr + 32] = e2 * c + e1 * si;
        acc1 += e1;
        acc2 += e2;
    }
    __shared__ float r1[256], r2[256];
    r1[tid] = acc1;
    r2[tid] = acc2;
    __syncthreads();
    if (tid < 32) {
        float s1 = 0.0f, s2 = 0.0f;
#pragma unroll
        for (int g = 0; g < 8; g++) { s1 += r1[tid + 32 * g]; s2 += r2[tid + 32 * g]; }
        g_Kpart[split][bh * 64 + tid]      = s1;
        g_Kpart[split][bh * 64 + tid + 32] = s2;
    }
}

// ---------------- Mpart[split][bh] = K_rot[slice]^T @ V[slice]  (64x64) ----------------
__global__ __launch_bounds__(256)
void compute_mpart_kernel() {
    const int bh = blockIdx.x, split = blockIdx.y;
    const int b = bh >> 4, h = bh & 15;
    __shared__ float Ksm[16][64];
    __shared__ float Vsm[16][68];
    const int tid = threadIdx.x;
    const int ti = tid >> 4;
    const int td = tid & 15;
    const int lrow = tid >> 4;
    const int lc = (tid & 15) * 4;

    float acc[4][4];
#pragma unroll
    for (int i = 0; i < 4; i++)
#pragma unroll
        for (int j = 0; j < 4; j++) acc[i][j] = 0.0f;

    for (int kt = 0; kt < 8; kt++) {
        int s = split * 128 + kt * 16 + lrow;
        const float* kp = &g_KV[(b * Sc + s) * 2048 + h * 64 + lc];
        float4 kv = *(const float4*)kp;
        float4 vv = *(const float4*)(kp + 1024);
        *(float4*)&Ksm[lrow][lc] = kv;
        *(float4*)&Vsm[lrow][lc] = vv;
        __syncthreads();
#pragma unroll
        for (int k = 0; k < 16; k++) {
            float4 a4 = *(const float4*)&Ksm[k][ti * 4];
            float4 b4 = *(const float4*)&Vsm[k][td * 4];
            float a[4] = {a4.x, a4.y, a4.z, a4.w};
            float bb[4] = {b4.x, b4.y, b4.z, b4.w};
#pragma unroll
            for (int i = 0; i < 4; i++)
#pragma unroll
                for (int j = 0; j < 4; j++) acc[i][j] += a[i] * bb[j];
        }
        __syncthreads();
    }
    float* mp = &g_Mpart[split][bh * 4096];
#pragma unroll
    for (int i = 0; i < 4; i++) {
        float4 o = make_float4(acc[i][0], acc[i][1], acc[i][2], acc[i][3]);
        *(float4*)&mp[(ti * 4 + i) * 64 + td * 4] = o;
    }
}

// ---------------- reduce split-K partials (deterministic) ----------------
__global__ void reduce_parts_kernel() {
    int idx = blockIdx.x * 256 + threadIdx.x;
    if (idx < BHc * 4096) {
        float s = 0.0f;
#pragma unroll
        for (int sp = 0; sp < NSPLIT; sp++) s += g_Mpart[sp][idx];
        g_M[idx] = s;
    } else if (idx < BHc * 4096 + BHc * 64) {
        int i2 = idx - BHc * 4096;
        float s = 0.0f;
#pragma unroll
        for (int sp = 0; sp < NSPLIT; sp++) s += g_Kpart[sp][i2];
        g_Ksum[i2] = s;
    }
}

// ---------------- y = (rope(elu(Q)+1) @ M) / (elu(Q)+1 . Ksum) ----------------
__global__ __launch_bounds__(256)
void compute_y_kernel() {
    const int bh = blockIdx.x, tchunk = blockIdx.y;
    const int b = bh >> 4, h = bh & 15;
    const int t0 = tchunk * 64;
    __shared__ float smA[64 * 65];
    __shared__ float qrot[64 * 65];
    __shared__ float ks[64];
    __shared__ float den[64];
    const int tid = threadIdx.x;

    if (tid < 64) ks[tid] = g_Ksum[bh * 64 + tid];

#pragma unroll
    for (int it = 0; it < 4; it++) {
        int idx = tid + it * 256;
        int r = idx >> 4, c4 = (idx & 15) * 4;
        float4 qv = *(const float4*)&g_Q[(b * Tc + t0 + r) * 1024 + h * 64 + c4];
        smA[r * 65 + c4 + 0] = eluplus(qv.x);
        smA[r * 65 + c4 + 1] = eluplus(qv.y);
        smA[r * 65 + c4 + 2] = eluplus(qv.z);
        smA[r * 65 + c4 + 3] = eluplus(qv.w);
    }
    __syncthreads();

#pragma unroll
    for (int it = 0; it < 8; it++) {
        int idx = tid + it * 256;
        int r = idx >> 5, j = idx & 31;
        float e1 = smA[r * 65 + j], e2 = smA[r * 65 + j + 32];
        int t = t0 + r;
        float c = g_cos[t * 32 + j], si = g_sin[t * 32 + j];
        qrot[r * 65 + j]      = e1 * c - e2 * si;
        qrot[r * 65 + j + 32] = e2 * c + e1 * si;
    }
    if (tid < 64) {
        float s = 0.0f;
#pragma unroll
        for (int d = 0; d < 64; d++) s += smA[tid * 65 + d] * ks[d];
        den[tid] = s;
    }
    __syncthreads();

#pragma unroll
    for (int it = 0; it < 16; it++) {
        int idx = tid + it * 256;
        smA[idx] = g_M[bh * 4096 + idx];
    }
    __syncthreads();

    const int row = tid >> 2;
    const int dg = (tid & 3) * 16;
    float acc[16];
#pragma unroll
    for (int i = 0; i < 16; i++) acc[i] = 0.0f;
#pragma unroll
    for (int k = 0; k < 64; k++) {
        float qv = qrot[row * 65 + k];
#pragma unroll
        for (int q = 0; q < 4; q++) {
            float4 mv = *(const float4*)&smA[k * 64 + dg + q * 4];
            acc[q * 4 + 0] += qv * mv.x;
            acc[q * 4 + 1] += qv * mv.y;
            acc[q * 4 + 2] += qv * mv.z;
            acc[q * 4 + 3] += qv * mv.w;
        }
    }
    float inv = 1.0f / den[row];
    float* yp = &g_Y[(b * Tc + t0 + row) * 1024 + h * 64 + dg];
#pragma unroll
    for (int q = 0; q < 4; q++) {
        float4 o = make_float4(acc[q * 4 + 0] * inv, acc[q * 4 + 1] * inv,
                               acc[q * 4 + 2] * inv, acc[q * 4 + 3] * inv);
        *(float4*)(yp + q * 4) = o;
    }
}

// ---------------- launch ----------------
extern "C" void kernel_launch(void* const* d_in, const int* in_sizes, int n_in,
                              void* d_out, int out_size) {
    const float* x      = (const float*)d_in[0];
    const float* memory = (const float*)d_in[1];
    const float* q_w    = (const float*)d_in[2];
    const float* q_b    = (const float*)d_in[3];
    const float* kv_w   = (const float*)d_in[4];
    const float* kv_b   = (const float*)d_in[5];
    const float* proj_w = (const float*)d_in[6];
    const float* proj_b = (const float*)d_in[7];
    float* out = (float*)d_out;

    float *pQ, *pKV, *pY;
    cudaGetSymbolAddress((void**)&pQ,  g_Q);
    cudaGetSymbolAddress((void**)&pKV, g_KV);
    cudaGetSymbolAddress((void**)&pY,  g_Y);

    // rope tables (independent)
    rope_table_kernel<<<(Sc * 32 + 255) / 256, 256>>>();

    // KV = memory @ kv_w + kv_b   [4096, 2048]
    gemm_bf16x3_kernel<<<dim3(2048 / BN, 4096 / BM), 256>>>(memory, kv_w, kv_b, pKV,
                                                            Bc * Sc, 2 * Cc, Cc);
    // Q = x @ q_w + q_b           [4096, 1024]
    gemm_bf16x3_kernel<<<dim3(1024 / BN, 4096 / BM), 256>>>(x, q_w, q_b, pQ,
                                                            Bc * Tc, Cc, Cc);
    // K -> elu+1 -> rope (in place), partial Ksum
    prep_k_kernel<<<dim3(BHc, NSPLIT), 256>>>();
    // M partials = K_rot^T V
    compute_mpart_kernel<<<dim3(BHc, NSPLIT), 256>>>();
    // reduce partials
    reduce_parts_kernel<<<(BHc * 4096 + BHc * 64 + 255) / 256, 256>>>();
    // per-head linear attention
    compute_y_kernel<<<dim3(BHc, Tc / 64), 256>>>();
    // out = Y @ proj_w + proj_b   [4096, 1024]
    gemm_bf16x3_kernel<<<dim3(1024 / BN, 4096 / BM), 256>>>(pY, proj_w, proj_b, out,
                                                            Bc * Tc, Cc, Cc);
}

// round 7
// speedup vs baseline: 2.0144x; 1.5750x over previous
#include <cuda_runtime.h>
#include <cuda_bf16.h>
#include <cstdint>
#include <math.h>

// Shapes (fixed by the problem)
#define Bc 2
#define Tc 2048
#define Sc 2048
#define Cc 1024
#define Hc 16
#define HDc 64
#define BHc (Bc*Hc)          // 32
#define NSPLIT 16

// ---------------- scratch (device globals; no allocation allowed) ----------------
__device__ float g_Q [Bc*Tc*Cc];                 // Q projection (fp32)      16 MB
__device__ float g_KV[Bc*Sc*2*Cc];               // KV projection (fp32)     32 MB
__device__ float g_cos[Sc*32];
__device__ float g_sin[Sc*32];
__device__ float g_Kpart[NSPLIT][BHc*HDc];
__device__ float g_Ksum [BHc*HDc];
__device__ float g_Mpart[NSPLIT][BHc*HDc*HDc];
__device__ float g_M    [BHc*HDc*HDc];

// bf16 hi/lo split operands (all K-major, K = 1024)
__device__ __nv_bfloat16 g_xhi[Bc*Tc*Cc],  g_xlo[Bc*Tc*Cc];       // x
__device__ __nv_bfloat16 g_mhi[Bc*Sc*Cc],  g_mlo[Bc*Sc*Cc];       // memory
__device__ __nv_bfloat16 g_yhi[Bc*Tc*Cc],  g_ylo[Bc*Tc*Cc];       // attention out
__device__ __nv_bfloat16 g_kvwt_hi[2*Cc*Cc], g_kvwt_lo[2*Cc*Cc];  // kv_w^T [2048,1024]
__device__ __nv_bfloat16 g_qwt_hi [Cc*Cc],   g_qwt_lo [Cc*Cc];    // q_w^T
__device__ __nv_bfloat16 g_pwt_hi [Cc*Cc],   g_pwt_lo [Cc*Cc];    // proj_w^T

__device__ __forceinline__ float eluplus(float x) {
    return x > 0.0f ? x + 1.0f : expf(x);
}

// ================= mma.sync helpers (sm_80 baseline; safe on compute_103) =================
__device__ __forceinline__ uint32_t smem_u32(const void* p) {
    uint32_t a;
    asm("{ .reg .u64 t; cvta.to.shared.u64 t, %1; cvt.u32.u64 %0, t; }" : "=r"(a) : "l"(p));
    return a;
}
__device__ __forceinline__ void cpa16(uint32_t dst, const void* src) {
    asm volatile("cp.async.cg.shared.global [%0], [%1], 16;" :: "r"(dst), "l"(src));
}
__device__ __forceinline__ void ldsm_x4(uint32_t* r, uint32_t addr) {
    asm volatile("ldmatrix.sync.aligned.m8n8.x4.shared.b16 {%0,%1,%2,%3}, [%4];"
        : "=r"(r[0]), "=r"(r[1]), "=r"(r[2]), "=r"(r[3]) : "r"(addr));
}
__device__ __forceinline__ void ldsm_x2(uint32_t* r, uint32_t addr) {
    asm volatile("ldmatrix.sync.aligned.m8n8.x2.shared.b16 {%0,%1}, [%2];"
        : "=r"(r[0]), "=r"(r[1]) : "r"(addr));
}
__device__ __forceinline__ void mma16816(float* c, const uint32_t* a, const uint32_t* b) {
    asm volatile("mma.sync.aligned.m16n8k16.row.col.f32.bf16.bf16.f32 "
        "{%0,%1,%2,%3}, {%4,%5,%6,%7}, {%8,%9}, {%0,%1,%2,%3};"
        : "+f"(c[0]), "+f"(c[1]), "+f"(c[2]), "+f"(c[3])
        : "r"(a[0]), "r"(a[1]), "r"(a[2]), "r"(a[3]), "r"(b[0]), "r"(b[1]));
}

// ================= bf16x3 HMMA GEMM: C[M,N] = A[M,K] @ B[N,K]^T + bias =================
// Tile 128x128, BK=32, K=1024 fixed, 4-stage cp.async pipeline.
// smem rows padded to 40 bf16 (80 B) -> conflict-free ldmatrix + cp.async.
#define GBM 128
#define GBN 128
#define GBK 32
#define GK  1024
#define GNIT (GK / GBK)            // 32
#define ROWB 80                    // bytes per smem row (32 bf16 + 8 pad)
#define MAT_BYTES (128 * ROWB)     // 10240
#define OFF_AH 0
#define OFF_AL (MAT_BYTES)
#define OFF_BH (2 * MAT_BYTES)
#define OFF_BL (3 * MAT_BYTES)
#define STAGE_BYTES (4 * MAT_BYTES)   // 40960
#define NSTAGE 4
#define SM_TOTAL (NSTAGE * STAGE_BYTES)  // 163840

__global__ __launch_bounds__(256, 1)
void tc_gemm(const __nv_bfloat16* __restrict__ Ah, const __nv_bfloat16* __restrict__ Al,
             const __nv_bfloat16* __restrict__ Bh, const __nv_bfloat16* __restrict__ Bl,
             const float* __restrict__ bias, float* __restrict__ C, int N) {
    extern __shared__ char smem[];
    const uint32_t sb = smem_u32(smem);
    const int tid = threadIdx.x, wid = tid >> 5, lane = tid & 31;
    const int wm = wid >> 2, wn = wid & 3;             // 2 x 4 warp grid
    const int m0 = blockIdx.y * GBM, n0 = blockIdx.x * GBN;

    float acc[4][4][4];
#pragma unroll
    for (int i = 0; i < 4; i++)
#pragma unroll
        for (int j = 0; j < 4; j++)
#pragma unroll
            for (int q = 0; q < 4; q++) acc[i][j][q] = 0.0f;

    // loader mapping: 512 16B-chunks per 128x32 matrix; thread does 2 per matrix
    const int lrow0 = tid >> 2;            // 0..63  (+64)
    const int lsub  = (tid & 3) * 8;       // bf16 offset within row (0,8,16,24)
    const uint32_t ldst0 = (uint32_t)(lrow0 * ROWB + lsub * 2);
    const uint32_t ldst1 = ldst0 + 64 * ROWB;

    auto prefetch = [&](int it) {
        const int st = it & (NSTAGE - 1);
        const int k0 = it * GBK;
        const uint32_t base = sb + st * STAGE_BYTES;
        const size_t asrc0 = (size_t)(m0 + lrow0) * GK + k0 + lsub;
        const size_t asrc1 = asrc0 + (size_t)64 * GK;
        const size_t bsrc0 = (size_t)(n0 + lrow0) * GK + k0 + lsub;
        const size_t bsrc1 = bsrc0 + (size_t)64 * GK;
        cpa16(base + OFF_AH + ldst0, Ah + asrc0);
        cpa16(base + OFF_AH + ldst1, Ah + asrc1);
        cpa16(base + OFF_AL + ldst0, Al + asrc0);
        cpa16(base + OFF_AL + ldst1, Al + asrc1);
        cpa16(base + OFF_BH + ldst0, Bh + bsrc0);
        cpa16(base + OFF_BH + ldst1, Bh + bsrc1);
        cpa16(base + OFF_BL + ldst0, Bl + bsrc0);
        cpa16(base + OFF_BL + ldst1, Bl + bsrc1);
        asm volatile("cp.async.commit_group;" ::: "memory");
    };

    prefetch(0); prefetch(1); prefetch(2);

    // fragment smem addresses (relative to stage base)
    const uint32_t a_rb = (uint32_t)((wm * 64 + (lane & 15)) * ROWB + (lane >> 4) * 16);
    const uint32_t b_rb = (uint32_t)((wn * 32 + (lane & 7)) * ROWB + ((lane >> 3) & 1) * 16);

    for (int it = 0; it < GNIT; it++) {
        if (it + 3 < GNIT)      { asm volatile("cp.async.wait_group 2;" ::: "memory"); }
        else if (it + 2 < GNIT) { asm volatile("cp.async.wait_group 1;" ::: "memory"); }
        else                    { asm volatile("cp.async.wait_group 0;" ::: "memory"); }
        __syncthreads();
        if (it + 3 < GNIT) prefetch(it + 3);

        const uint32_t base = sb + (it & (NSTAGE - 1)) * STAGE_BYTES;
#pragma unroll
        for (int kk = 0; kk < 2; kk++) {               // two k16 steps per BK=32
            const uint32_t koff = (uint32_t)(kk * 32);  // 16 bf16 = 32 bytes
            uint32_t ah[4][4], al[4][4], bh[4][2], bl[4][2];
#pragma unroll
            for (int mf = 0; mf < 4; mf++) {
                uint32_t ad = base + a_rb + (uint32_t)(mf * 16 * ROWB) + koff;
                ldsm_x4(ah[mf], ad + OFF_AH);
                ldsm_x4(al[mf], ad + OFF_AL);
            }
#pragma unroll
            for (int nf = 0; nf < 4; nf++) {
                uint32_t bd = base + b_rb + (uint32_t)(nf * 8 * ROWB) + koff;
                ldsm_x2(bh[nf], bd + OFF_BH);
                ldsm_x2(bl[nf], bd + OFF_BL);
            }
#pragma unroll
            for (int mf = 0; mf < 4; mf++)
#pragma unroll
                for (int nf = 0; nf < 4; nf++) {
                    mma16816(acc[mf][nf], ah[mf], bh[nf]);
                    mma16816(acc[mf][nf], ah[mf], bl[nf]);
                    mma16816(acc[mf][nf], al[mf], bh[nf]);
                }
        }
    }

    // epilogue: direct stores with bias
#pragma unroll
    for (int mf = 0; mf < 4; mf++) {
        const int r0 = m0 + wm * 64 + mf * 16 + (lane >> 2);
#pragma unroll
        for (int nf = 0; nf < 4; nf++) {
            const int col = n0 + wn * 32 + nf * 8 + (lane & 3) * 2;
            const float b0 = bias[col], b1 = bias[col + 1];
            float* p0 = C + (size_t)r0 * N + col;
            float2 v0 = make_float2(acc[mf][nf][0] + b0, acc[mf][nf][1] + b1);
            float2 v1 = make_float2(acc[mf][nf][2] + b0, acc[mf][nf][3] + b1);
            *(float2*)p0 = v0;
            *(float2*)(p0 + 8 * N) = v1;
        }
    }
}

// ---------------- operand preparation ----------------
__global__ void split_act_kernel(const float* __restrict__ A,
                                 __nv_bfloat16* __restrict__ hi,
                                 __nv_bfloat16* __restrict__ lo, int n4) {
    int i = blockIdx.x * 256 + threadIdx.x;
    if (i >= n4) return;
    float4 v = *(const float4*)(A + (size_t)i * 4);
    float f[4] = {v.x, v.y, v.z, v.w};
    __nv_bfloat16 h[4], l[4];
#pragma unroll
    for (int q = 0; q < 4; q++) {
        h[q] = __float2bfloat16(f[q]);
        l[q] = __float2bfloat16(f[q] - __bfloat162float(h[q]));
    }
    *(uint2*)(hi + (size_t)i * 4) = *(uint2*)h;
    *(uint2*)(lo + (size_t)i * 4) = *(uint2*)l;
}

__global__ void wtrans_split_kernel(const float* __restrict__ W,
                                    __nv_bfloat16* __restrict__ th,
                                    __nv_bfloat16* __restrict__ tl, int K, int N) {
    __shared__ float t[32][33];
    int k0 = blockIdx.y * 32, n0 = blockIdx.x * 32;
    int tx = threadIdx.x, ty = threadIdx.y;
#pragma unroll
    for (int i = ty; i < 32; i += 8)
        t[i][tx] = W[(size_t)(k0 + i) * N + n0 + tx];
    __syncthreads();
#pragma unroll
    for (int i = ty; i < 32; i += 8) {
        float v = t[tx][i];
        __nv_bfloat16 h = __float2bfloat16(v);
        size_t o = (size_t)(n0 + i) * K + k0 + tx;
        th[o] = h;
        tl[o] = __float2bfloat16(v - __bfloat162float(h));
    }
}

// ---------------- rope cos/sin table ----------------
__global__ void rope_table_kernel() {
    int idx = blockIdx.x * blockDim.x + threadIdx.x;
    if (idx >= Sc * 32) return;
    int t = idx >> 5, j = idx & 31;
    float ex = (float)(2 * j) / 64.0f;
    float invf = 1.0f / powf(10000.0f, ex);
    float ang = (float)t * invf;
    float s, c;
    sincosf(ang, &s, &c);
    g_cos[idx] = c;
    g_sin[idx] = s;
}

// ---------------- K: elu+1, rope in-place, partial column sums ----------------
__global__ __launch_bounds__(256)
void prep_k_kernel() {
    const int bh = blockIdx.x, split = blockIdx.y;
    const int b = bh >> 4, h = bh & 15;
    const int tid = threadIdx.x;
    const int j = tid & 31, sg = tid >> 5;
    float acc1 = 0.0f, acc2 = 0.0f;
#pragma unroll 4
    for (int it = 0; it < 16; it++) {
        int s = split * 128 + sg + it * 8;
        int addr = (b * Sc + s) * 2048 + h * 64 + j;
        float k1 = g_KV[addr], k2 = g_KV[addr + 32];
        float e1 = eluplus(k1), e2 = eluplus(k2);
        float c = g_cos[s * 32 + j], si = g_sin[s * 32 + j];
        g_KV[addr]      = e1 * c - e2 * si;
        g_KV[addr + 32] = e2 * c + e1 * si;
        acc1 += e1;
        acc2 += e2;
    }
    __shared__ float r1[256], r2[256];
    r1[tid] = acc1;
    r2[tid] = acc2;
    __syncthreads();
    if (tid < 32) {
        float s1 = 0.0f, s2 = 0.0f;
#pragma unroll
        for (int g = 0; g < 8; g++) { s1 += r1[tid + 32 * g]; s2 += r2[tid + 32 * g]; }
        g_Kpart[split][bh * 64 + tid]      = s1;
        g_Kpart[split][bh * 64 + tid + 32] = s2;
    }
}

// ---------------- Mpart[split][bh] = K_rot[slice]^T @ V[slice] ----------------
__global__ __launch_bounds__(256)
void compute_mpart_kernel() {
    const int bh = blockIdx.x, split = blockIdx.y;
    const int b = bh >> 4, h = bh & 15;
    __shared__ float Ksm[16][64];
    __shared__ float Vsm[16][68];
    const int tid = threadIdx.x;
    const int ti = tid >> 4, td = tid & 15;
    const int lrow = tid >> 4, lc = (tid & 15) * 4;

    float acc[4][4];
#pragma unroll
    for (int i = 0; i < 4; i++)
#pragma unroll
        for (int j = 0; j < 4; j++) acc[i][j] = 0.0f;

    for (int kt = 0; kt < 8; kt++) {
        int s = split * 128 + kt * 16 + lrow;
        const float* kp = &g_KV[(b * Sc + s) * 2048 + h * 64 + lc];
        float4 kv = *(const float4*)kp;
        float4 vv = *(const float4*)(kp + 1024);
        *(float4*)&Ksm[lrow][lc] = kv;
        *(float4*)&Vsm[lrow][lc] = vv;
        __syncthreads();
#pragma unroll
        for (int k = 0; k < 16; k++) {
            float4 a4 = *(const float4*)&Ksm[k][ti * 4];
            float4 b4 = *(const float4*)&Vsm[k][td * 4];
            float a[4] = {a4.x, a4.y, a4.z, a4.w};
            float bb[4] = {b4.x, b4.y, b4.z, b4.w};
#pragma unroll
            for (int i = 0; i < 4; i++)
#pragma unroll
                for (int j = 0; j < 4; j++) acc[i][j] += a[i] * bb[j];
        }
        __syncthreads();
    }
    float* mp = &g_Mpart[split][bh * 4096];
#pragma unroll
    for (int i = 0; i < 4; i++) {
        float4 o = make_float4(acc[i][0], acc[i][1], acc[i][2], acc[i][3]);
        *(float4*)&mp[(ti * 4 + i) * 64 + td * 4] = o;
    }
}

// ---------------- reduce split-K partials (deterministic) ----------------
__global__ void reduce_parts_kernel() {
    int idx = blockIdx.x * 256 + threadIdx.x;
    if (idx < BHc * 4096) {
        float s = 0.0f;
#pragma unroll
        for (int sp = 0; sp < NSPLIT; sp++) s += g_Mpart[sp][idx];
        g_M[idx] = s;
    } else if (idx < BHc * 4096 + BHc * 64) {
        int i2 = idx - BHc * 4096;
        float s = 0.0f;
#pragma unroll
        for (int sp = 0; sp < NSPLIT; sp++) s += g_Kpart[sp][i2];
        g_Ksum[i2] = s;
    }
}

// ---------------- y = (rope(elu(Q)+1) @ M) / (elu(Q)+1 . Ksum) -> bf16 hi/lo ----------------
__global__ __launch_bounds__(256)
void compute_y_kernel() {
    const int bh = blockIdx.x, tchunk = blockIdx.y;
    const int b = bh >> 4, h = bh & 15;
    const int t0 = tchunk * 64;
    __shared__ float smA[64 * 65];
    __shared__ float qrot[64 * 65];
    __shared__ float ks[64];
    __shared__ float den[64];
    const int tid = threadIdx.x;

    if (tid < 64) ks[tid] = g_Ksum[bh * 64 + tid];

#pragma unroll
    for (int it = 0; it < 4; it++) {
        int idx = tid + it * 256;
        int r = idx >> 4, c4 = (idx & 15) * 4;
        float4 qv = *(const float4*)&g_Q[(b * Tc + t0 + r) * 1024 + h * 64 + c4];
        smA[r * 65 + c4 + 0] = eluplus(qv.x);
        smA[r * 65 + c4 + 1] = eluplus(qv.y);
        smA[r * 65 + c4 + 2] = eluplus(qv.z);
        smA[r * 65 + c4 + 3] = eluplus(qv.w);
    }
    __syncthreads();

#pragma unroll
    for (int it = 0; it < 8; it++) {
        int idx = tid + it * 256;
        int r = idx >> 5, j = idx & 31;
        float e1 = smA[r * 65 + j], e2 = smA[r * 65 + j + 32];
        int t = t0 + r;
        float c = g_cos[t * 32 + j], si = g_sin[t * 32 + j];
        qrot[r * 65 + j]      = e1 * c - e2 * si;
        qrot[r * 65 + j + 32] = e2 * c + e1 * si;
    }
    if (tid < 64) {
        float s = 0.0f;
#pragma unroll
        for (int d = 0; d < 64; d++) s += smA[tid * 65 + d] * ks[d];
        den[tid] = s;
    }
    __syncthreads();

#pragma unroll
    for (int it = 0; it < 16; it++) {
        int idx = tid + it * 256;
        smA[idx] = g_M[bh * 4096 + idx];
    }
    __syncthreads();

    const int row = tid >> 2;
    const int dg = (tid & 3) * 16;
    float acc[16];
#pragma unroll
    for (int i = 0; i < 16; i++) acc[i] = 0.0f;
#pragma unroll
    for (int k = 0; k < 64; k++) {
        float qv = qrot[row * 65 + k];
#pragma unroll
        for (int q = 0; q < 4; q++) {
            float4 mv = *(const float4*)&smA[k * 64 + dg + q * 4];
            acc[q * 4 + 0] += qv * mv.x;
            acc[q * 4 + 1] += qv * mv.y;
            acc[q * 4 + 2] += qv * mv.z;
            acc[q * 4 + 3] += qv * mv.w;
        }
    }
    float inv = 1.0f / den[row];
    size_t yoff = (size_t)(b * Tc + t0 + row) * 1024 + h * 64 + dg;
    __nv_bfloat16 hv[16], lv[16];
#pragma unroll
    for (int i = 0; i < 16; i++) {
        float o = acc[i] * inv;
        hv[i] = __float2bfloat16(o);
        lv[i] = __float2bfloat16(o - __bfloat162float(hv[i]));
    }
    *(uint4*)(g_yhi + yoff)     = *(uint4*)hv;
    *(uint4*)(g_yhi + yoff + 8) = *(uint4*)(hv + 8);
    *(uint4*)(g_ylo + yoff)     = *(uint4*)lv;
    *(uint4*)(g_ylo + yoff + 8) = *(uint4*)(lv + 8);
}

// ---------------- launch ----------------
extern "C" void kernel_launch(void* const* d_in, const int* in_sizes, int n_in,
                              void* d_out, int out_size) {
    const float* x      = (const float*)d_in[0];
    const float* memory = (const float*)d_in[1];
    const float* q_w    = (const float*)d_in[2];
    const float* q_b    = (const float*)d_in[3];
    const float* kv_w   = (const float*)d_in[4];
    const float* kv_b   = (const float*)d_in[5];
    const float* proj_w = (const float*)d_in[6];
    const float* proj_b = (const float*)d_in[7];
    float* out = (float*)d_out;

    cudaFuncSetAttribute(tc_gemm, cudaFuncAttributeMaxDynamicSharedMemorySize, SM_TOTAL);

    float *pQ, *pKV;
    cudaGetSymbolAddress((void**)&pQ,  g_Q);
    cudaGetSymbolAddress((void**)&pKV, g_KV);
    __nv_bfloat16 *xh, *xl, *mh, *ml, *yh, *yl, *kwh, *kwl, *qwh, *qwl, *pwh, *pwl;
    cudaGetSymbolAddress((void**)&xh, g_xhi);  cudaGetSymbolAddress((void**)&xl, g_xlo);
    cudaGetSymbolAddress((void**)&mh, g_mhi);  cudaGetSymbolAddress((void**)&ml, g_mlo);
    cudaGetSymbolAddress((void**)&yh, g_yhi);  cudaGetSymbolAddress((void**)&yl, g_ylo);
    cudaGetSymbolAddress((void**)&kwh, g_kvwt_hi); cudaGetSymbolAddress((void**)&kwl, g_kvwt_lo);
    cudaGetSymbolAddress((void**)&qwh, g_qwt_hi);  cudaGetSymbolAddress((void**)&qwl, g_qwt_lo);
    cudaGetSymbolAddress((void**)&pwh, g_pwt_hi);  cudaGetSymbolAddress((void**)&pwl, g_pwt_lo);

    rope_table_kernel<<<(Sc * 32 + 255) / 256, 256>>>();

    // operand prep
    wtrans_split_kernel<<<dim3(2 * Cc / 32, Cc / 32), dim3(32, 8)>>>(kv_w, kwh, kwl, Cc, 2 * Cc);
    wtrans_split_kernel<<<dim3(Cc / 32, Cc / 32), dim3(32, 8)>>>(q_w, qwh, qwl, Cc, Cc);
    wtrans_split_kernel<<<dim3(Cc / 32, Cc / 32), dim3(32, 8)>>>(proj_w, pwh, pwl, Cc, Cc);
    split_act_kernel<<<(Bc * Sc * Cc / 4 + 255) / 256, 256>>>(memory, mh, ml, Bc * Sc * Cc / 4);
    split_act_kernel<<<(Bc * Tc * Cc / 4 + 255) / 256, 256>>>(x, xh, xl, Bc * Tc * Cc / 4);

    // KV = memory @ kv_w + kv_b
    tc_gemm<<<dim3(2 * Cc / GBN, Bc * Sc / GBM), 256, SM_TOTAL>>>(mh, ml, kwh, kwl, kv_b, pKV, 2 * Cc);
    // Q = x @ q_w + q_b
    tc_gemm<<<dim3(Cc / GBN, Bc * Tc / GBM), 256, SM_TOTAL>>>(xh, xl, qwh, qwl, q_b, pQ, Cc);

    prep_k_kernel<<<dim3(BHc, NSPLIT), 256>>>();
    compute_mpart_kernel<<<dim3(BHc, NSPLIT), 256>>>();
    reduce_parts_kernel<<<(BHc * 4096 + BHc * 64 + 255) / 256, 256>>>();
    compute_y_kernel<<<dim3(BHc, Tc / 64), 256>>>();

    // out = Y @ proj_w + proj_b
    tc_gemm<<<dim3(Cc / GBN, Bc * Tc / GBM), 256, SM_TOTAL>>>(yh, yl, pwh, pwl, proj_b, out, Cc);
}